// round 12
// baseline (speedup 1.0000x reference)
#include <cuda_runtime.h>
#include <math.h>
#include <stdint.h>

#define NTOK 1024
#define DMOD 2048
#define NHEAD 8
#define DH 256
#define NLAY 3
#define MM 16
#define KSEL 8
#define DFFN 2048
#define DECH 1024
#define NCLS1 35

static constexpr size_t ND_ = (size_t)NTOK * DMOD;
static constexpr size_t OFF_SFEAT = 0, OFF_QH = ND_, OFF_KH = 2*ND_, OFF_VH = 3*ND_,
    OFF_O = 4*ND_, OFF_P = 5*ND_, OFF_X = 6*ND_, OFF_F = 7*ND_, OFF_F2 = 8*ND_,
    OFF_C1 = 9*ND_, OFF_C2 = 10*ND_, OFF_ATT = 11*ND_;
static constexpr size_t OFF_HD  = OFF_ATT + (size_t)NHEAD*NTOK*NTOK;
static constexpr size_t OFF_HBN = OFF_HD + (size_t)NTOK*DECH;
static constexpr size_t SCR_FLOATS = OFF_HBN + (size_t)NTOK*DECH;
__device__ float g_scratch[SCR_FLOATS];

__device__ __forceinline__ float warpSum(float v) {
#pragma unroll
    for (int o = 16; o; o >>= 1) v += __shfl_down_sync(0xffffffffu, v, o);
    return v;
}
__device__ __forceinline__ float warpMax(float v) {
#pragma unroll
    for (int o = 16; o; o >>= 1) v = fmaxf(v, __shfl_down_sync(0xffffffffu, v, o));
    return v;
}
__device__ float blockSum(float v) {
    __shared__ float s[8];
    int lane = threadIdx.x & 31, w = threadIdx.x >> 5;
    v = warpSum(v);
    if (lane == 0) s[w] = v;
    __syncthreads();
    float r = 0.f;
    if (w == 0) { r = (lane < 8) ? s[lane] : 0.f; r = warpSum(r); }
    __syncthreads();
    return r;
}
__device__ float blockMax(float v) {
    __shared__ float s[8];
    int lane = threadIdx.x & 31, w = threadIdx.x >> 5;
    v = warpMax(v);
    if (lane == 0) s[w] = v;
    __syncthreads();
    float r = -1e30f;
    if (w == 0) { r = (lane < 8) ? s[lane] : -1e30f; r = warpMax(r); }
    __syncthreads();
    return r;
}

#define PECOEF (-0.008994473019508232f)

__global__ void selector_k(const float* __restrict__ feat, const int* __restrict__ fid,
                           const int* __restrict__ mn, float* __restrict__ sf) {
    int n = blockIdx.x, tid = threadIdx.x;
    __shared__ int nodes[MM], pos[MM], sel[KSEL];
    __shared__ float sc[MM], wgt[KSEL];
    if (tid < MM) nodes[tid] = mn[n * MM + tid];
    __syncthreads();
    if (tid == 0) {
        int p = 0, prev = fid[nodes[0]];
        pos[0] = 0;
        for (int m = 1; m < MM; m++) {
            int f = fid[nodes[m]];
            if (f != prev) { p++; prev = f; }
            pos[m] = p;
        }
    }
    __syncthreads();
    const float* fn = feat + (size_t)n * DMOD;
    float part[MM];
#pragma unroll
    for (int m = 0; m < MM; m++) part[m] = 0.f;
    for (int d = tid; d < DMOD; d += 256) {
        float fv = fn[d];
        float fr = expf((float)(d >> 1) * PECOEF);
        bool odd = d & 1;
#pragma unroll
        for (int m = 0; m < MM; m++) {
            float ang = (float)pos[m] * fr;
            float pev = odd ? cosf(ang) : sinf(ang);
            part[m] += fv * (feat[(size_t)nodes[m] * DMOD + d] + pev);
        }
    }
    for (int m = 0; m < MM; m++) {
        float ts = blockSum(part[m]);
        if (tid == 0) sc[m] = ts * 0.022097086912079608f;
    }
    __syncthreads();
    if (tid == 0) {
        unsigned used = 0;
        float tv[KSEL];
        for (int k = 0; k < KSEL; k++) {
            float best = -1e30f; int bi = 0;
            for (int m = 0; m < MM; m++)
                if (!((used >> m) & 1) && sc[m] > best) { best = sc[m]; bi = m; }
            used |= 1u << bi; sel[k] = bi; tv[k] = best;
        }
        float mx = tv[0], ssum = 0.f;
        for (int k = 0; k < KSEL; k++) { wgt[k] = expf(tv[k] - mx); ssum += wgt[k]; }
        for (int k = 0; k < KSEL; k++) wgt[k] /= ssum;
    }
    __syncthreads();
    float* po = sf + (size_t)n * DMOD;
    for (int d = tid; d < DMOD; d += 256) {
        float fr = expf((float)(d >> 1) * PECOEF);
        bool odd = d & 1;
        float acc = 0.f;
#pragma unroll
        for (int k = 0; k < KSEL; k++) {
            int m = sel[k];
            float ang = (float)pos[m] * fr;
            float pev = odd ? cosf(ang) : sinf(ang);
            acc += wgt[k] * (feat[(size_t)nodes[m] * DMOD + d] + pev);
        }
        po[d] = acc;
    }
}

// ===== bf16-3-product GEMM, 64x64 CTA tile, 128 threads, 4 CTAs/SM =====
__device__ __forceinline__ uint32_t smem_u32(const void* p) {
    uint32_t a;
    asm("{ .reg .u64 t; cvta.to.shared.u64 t, %1; cvt.u32.u64 %0, t; }" : "=r"(a) : "l"(p));
    return a;
}
__device__ __forceinline__ float bf_lo(uint32_t w) { return __uint_as_float(w << 16); }
__device__ __forceinline__ float bf_hi(uint32_t w) { return __uint_as_float(w & 0xffff0000u); }
__device__ __forceinline__ uint32_t packbf(float x, float y) {
    uint32_t r;
    asm("cvt.rn.satfinite.bf16x2.f32 %0, %1, %2;" : "=r"(r) : "f"(y), "f"(x));
    return r;
}
__device__ __forceinline__ void split2(float x, float y, uint32_t& hi, uint32_t& lo) {
    hi = packbf(x, y);
    lo = packbf(x - bf_lo(hi), y - bf_hi(hi));
}
__device__ __forceinline__ void sts128(uint32_t a, uint32_t x, uint32_t y, uint32_t z, uint32_t w) {
    asm volatile("st.shared.v4.b32 [%0], {%1,%2,%3,%4};" :: "r"(a), "r"(x), "r"(y), "r"(z), "r"(w) : "memory");
}
__device__ __forceinline__ void sts32(uint32_t a, uint32_t x) {
    asm volatile("st.shared.b32 [%0], %1;" :: "r"(a), "r"(x) : "memory");
}
#define LDMX4(r0, r1, r2, r3, ad)                                             \
    asm volatile("ldmatrix.sync.aligned.m8n8.x4.shared.b16 {%0,%1,%2,%3}, [%4];" \
                 : "=r"(r0), "=r"(r1), "=r"(r2), "=r"(r3) : "r"(ad))
#define MMA_BF16(c, a, b)                                                     \
    asm volatile(                                                             \
        "mma.sync.aligned.m16n8k16.row.col.f32.bf16.bf16.f32 "                \
        "{%0,%1,%2,%3},{%4,%5,%6,%7},{%8,%9},{%0,%1,%2,%3};\n"                \
        : "+f"(c[0]), "+f"(c[1]), "+f"(c[2]), "+f"(c[3])                      \
        : "r"(a[0]), "r"(a[1]), "r"(a[2]), "r"(a[3]), "r"(b[0]), "r"(b[1]))

// stage 20480B: A_hi@0, A_lo@5120, B_hi@10240, B_lo@15360 (64 rows x 80B each); 2 stages
#define SMEM_BG 40960

// OM=0: C[bz*sC + m*ldc + n] | OM=1: bz*sC + split-head | OM=2: merge-head
template <bool TB, int OM, bool RELU>
__global__ void __launch_bounds__(128)
bgemm_k(const float* __restrict__ A0, const float* __restrict__ A1,
        const float* __restrict__ B,
        const float* __restrict__ bias, float* __restrict__ C,
        int K, int lda, int ldb, int ldc,
        long sA, long sB, long sC, long sBias, float scale) {
    extern __shared__ __align__(16) char sm8[];
    int bz = blockIdx.z;
    const float* Ab = ((bz == 0) ? A0 : A1) + (long)bz * sA;
    const float* Bb = B + (long)bz * sB;
    int m0 = blockIdx.y * 64, n0 = blockIdx.x * 64;
    int tid = threadIdx.x;
    int warpId = tid >> 5, lane = tid & 31;
    int g = lane >> 2, tig = lane & 3;
    int wm = warpId & 1, wn = warpId >> 1;        // 2 x 2 warps
    int mBase = wm * 32, nBase = wn * 32;         // warp tile 32 x 32
    uint32_t smb = smem_u32(sm8);

    int arow = tid >> 1, akh = (tid & 1) * 16;    // 64 rows, 2 thr/row (A; B when TB)
    int bkp = tid & 15, bnj = tid >> 4;           // B(!TB): k-pair 0..15, n-octet 0..7

    float4 la[4], lb[4];
    auto ldgChunk = [&](int ch) {
        int k0 = ch << 5;
        const float4* ap = (const float4*)(Ab + (long)(m0 + arow) * lda + k0 + akh);
        la[0] = ap[0]; la[1] = ap[1]; la[2] = ap[2]; la[3] = ap[3];
        if (TB) {
            const float4* bp = (const float4*)(Bb + (long)(n0 + arow) * ldb + k0 + akh);
            lb[0] = bp[0]; lb[1] = bp[1]; lb[2] = bp[2]; lb[3] = bp[3];
        } else {
            const float4* bp = (const float4*)(Bb + (long)(k0 + 2 * bkp) * ldb + n0 + bnj * 8);
            lb[0] = bp[0]; lb[1] = bp[1];
            const float4* bp2 = (const float4*)(Bb + (long)(k0 + 2 * bkp + 1) * ldb + n0 + bnj * 8);
            lb[2] = bp2[0]; lb[3] = bp2[1];
        }
    };
    auto stsChunk = [&](int st) {
        uint32_t sb = smb + (uint32_t)st * 20480u;
        uint32_t hi[8], lo[8];
        const float* fa = (const float*)la;
#pragma unroll
        for (int i = 0; i < 8; i++) split2(fa[2 * i], fa[2 * i + 1], hi[i], lo[i]);
        uint32_t aoff = sb + (uint32_t)(arow * 80 + akh * 2);
        sts128(aoff,           hi[0], hi[1], hi[2], hi[3]);
        sts128(aoff + 16u,     hi[4], hi[5], hi[6], hi[7]);
        sts128(aoff + 5120u,       lo[0], lo[1], lo[2], lo[3]);
        sts128(aoff + 5120u + 16u, lo[4], lo[5], lo[6], lo[7]);
        const float* fb = (const float*)lb;
        if (TB) {
#pragma unroll
            for (int i = 0; i < 8; i++) split2(fb[2 * i], fb[2 * i + 1], hi[i], lo[i]);
            uint32_t boff = sb + 10240u + (uint32_t)(arow * 80 + akh * 2);
            sts128(boff,           hi[0], hi[1], hi[2], hi[3]);
            sts128(boff + 16u,     hi[4], hi[5], hi[6], hi[7]);
            sts128(boff + 5120u,       lo[0], lo[1], lo[2], lo[3]);
            sts128(boff + 5120u + 16u, lo[4], lo[5], lo[6], lo[7]);
        } else {
#pragma unroll
            for (int n = 0; n < 8; n++) {
                uint32_t h, l;
                split2(fb[n], fb[8 + n], h, l);
                uint32_t boff = sb + 10240u + (uint32_t)((bnj * 8 + n) * 80 + bkp * 4);
                sts32(boff, h);
                sts32(boff + 5120u, l);
            }
        }
    };

    float acc[2][4][4];
#pragma unroll
    for (int i = 0; i < 2; i++)
#pragma unroll
        for (int j = 0; j < 4; j++)
#pragma unroll
            for (int r = 0; r < 4; r++) acc[i][j][r] = 0.f;

    int lrow = lane & 7, lgrp = lane >> 3;
    auto compute = [&](int st) {
        uint32_t sb = smb + (uint32_t)st * 20480u;
#pragma unroll
        for (int ks = 0; ks < 2; ks++) {
            uint32_t bhi[4][2], blo[4][2];
            int kbB = ks * 32 + (lgrp & 1) * 16;
            int rB = (lgrp >> 1) * 8 + lrow;
#pragma unroll
            for (int np = 0; np < 2; np++) {
                uint32_t bd = sb + 10240u + (uint32_t)((nBase + np * 16 + rB) * 80 + kbB);
                LDMX4(bhi[2*np][0], bhi[2*np][1], bhi[2*np+1][0], bhi[2*np+1][1], bd);
                LDMX4(blo[2*np][0], blo[2*np][1], blo[2*np+1][0], blo[2*np+1][1], bd + 5120u);
            }
            int kbA = ks * 32 + (lgrp >> 1) * 16;
            int rA = (lgrp & 1) * 8 + lrow;
#pragma unroll
            for (int mi = 0; mi < 2; mi++) {
                uint32_t ahi[4], alo[4];
                uint32_t ad = sb + (uint32_t)((mBase + mi * 16 + rA) * 80 + kbA);
                LDMX4(ahi[0], ahi[1], ahi[2], ahi[3], ad);
                LDMX4(alo[0], alo[1], alo[2], alo[3], ad + 5120u);
#pragma unroll
                for (int ni = 0; ni < 4; ni++) {
                    MMA_BF16(acc[mi][ni], ahi, bhi[ni]);
                    MMA_BF16(acc[mi][ni], ahi, blo[ni]);
                    MMA_BF16(acc[mi][ni], alo, bhi[ni]);
                }
            }
        }
    };

    int nc = K >> 5;
    ldgChunk(0);
    stsChunk(0);
    __syncthreads();
    for (int ch = 0; ch < nc; ch++) {
        if (ch + 1 < nc) ldgChunk(ch + 1);
        compute(ch & 1);
        if (ch + 1 < nc) stsChunk((ch + 1) & 1);  // other stage; prior readers fenced last iter
        __syncthreads();
    }

    const float* bp = bias ? (bias + (long)bz * sBias) : nullptr;
#pragma unroll
    for (int mi = 0; mi < 2; mi++) {
#pragma unroll
        for (int ni = 0; ni < 4; ni++) {
            int row0 = m0 + mBase + mi * 16 + g;
            int col0 = n0 + nBase + ni * 8 + tig * 2;
#pragma unroll
            for (int h = 0; h < 2; h++) {
                int row = row0 + 8 * h;
                float vx = acc[mi][ni][2 * h + 0] * scale;
                float vy = acc[mi][ni][2 * h + 1] * scale;
                if (bp) { vx += bp[col0]; vy += bp[col0 + 1]; }
                if (RELU) { vx = fmaxf(vx, 0.f); vy = fmaxf(vy, 0.f); }
                long idx;
                if (OM == 0)      idx = (long)bz * sC + (long)row * ldc + col0;
                else if (OM == 1) idx = (long)bz * sC + ((long)(col0 >> 8) * NTOK + row) * DH + (col0 & 255);
                else              idx = (long)row * DMOD + (long)bz * DH + col0;
                C[idx] = vx;
                C[idx + 1] = vy;
            }
        }
    }
}

__global__ void softmax_k(float* __restrict__ att) {
    float* row = att + (long)blockIdx.x * 1024;
    int tid = threadIdx.x;
    float v[4], mx = -1e30f;
#pragma unroll
    for (int i = 0; i < 4; i++) { v[i] = row[tid + i * 256]; mx = fmaxf(mx, v[i]); }
    float bm = blockMax(mx);
    __shared__ float sb, sv;
    if (tid == 0) sb = bm;
    __syncthreads();
    mx = sb;
    float s = 0.f;
#pragma unroll
    for (int i = 0; i < 4; i++) { v[i] = expf(v[i] - mx); s += v[i]; }
    float bs = blockSum(s);
    if (tid == 0) sv = 1.f / bs;
    __syncthreads();
#pragma unroll
    for (int i = 0; i < 4; i++) row[tid + i * 256] = v[i] * sv;
}

__global__ void addln_k(const float* __restrict__ a, const float* __restrict__ b,
                        const float* __restrict__ g, const float* __restrict__ be,
                        float* __restrict__ o) {
    int n = blockIdx.x, tid = threadIdx.x;
    const float* pa = a + (size_t)n * DMOD;
    const float* pb = b + (size_t)n * DMOD;
    float x[8], s = 0.f;
#pragma unroll
    for (int i = 0; i < 8; i++) { int d = tid + i * 256; x[i] = pa[d] + pb[d]; s += x[i]; }
    float ts = blockSum(s);
    __shared__ float mu, inv;
    if (tid == 0) mu = ts * (1.f / DMOD);
    __syncthreads();
    float m = mu, vs = 0.f;
#pragma unroll
    for (int i = 0; i < 8; i++) { float dv = x[i] - m; vs += dv * dv; }
    float tv = blockSum(vs);
    if (tid == 0) inv = rsqrtf(tv * (1.f / DMOD) + 1e-5f);
    __syncthreads();
    float iv = inv;
    float* po = o + (size_t)n * DMOD;
#pragma unroll
    for (int i = 0; i < 8; i++) { int d = tid + i * 256; po[d] = (x[i] - m) * iv * g[d] + be[d]; }
}

__global__ void bn_k(const float* __restrict__ h, const float* __restrict__ g,
                     const float* __restrict__ b, float* __restrict__ o) {
    int j = blockIdx.x, tid = threadIdx.x;
    float s = 0.f;
    for (int r = tid; r < NTOK; r += 256) s += h[(size_t)r * DECH + j];
    float ts = blockSum(s);
    __shared__ float mu, inv;
    if (tid == 0) mu = ts * (1.f / NTOK);
    __syncthreads();
    float m = mu, vs = 0.f;
    for (int r = tid; r < NTOK; r += 256) { float d = h[(size_t)r * DECH + j] - m; vs += d * d; }
    float tv = blockSum(vs);
    if (tid == 0) inv = rsqrtf(tv * (1.f / NTOK) + 1e-5f);
    __syncthreads();
    float iv = inv, gg = g[j], bb = b[j];
    for (int r = tid; r < NTOK; r += 256) {
        float v = (h[(size_t)r * DECH + j] - m) * iv * gg + bb;
        o[(size_t)r * DECH + j] = fmaxf(v, 0.f);
    }
}

__global__ void dec2_k(const float* __restrict__ hbn, const float* __restrict__ w,
                       const float* __restrict__ b, float* __restrict__ dist) {
    int idx = blockIdx.x * blockDim.x + threadIdx.x;
    if (idx >= NTOK * NCLS1) return;
    int n = idx / NCLS1, c = idx % NCLS1;
    const float* hr = hbn + (size_t)n * DECH;
    float s = 0.f;
    for (int j = 0; j < DECH; j++) s = fmaf(hr[j], w[(size_t)j * NCLS1 + c], s);
    dist[idx] = s + b[c];
}

extern "C" void kernel_launch(void* const* d_in, const int* in_sizes, int n_in,
                              void* d_out, int out_size) {
    const float* feat = (const float*)d_in[0];
    const int* fid = (const int*)d_in[1];
    const int* mn = (const int*)d_in[2];
    const float *t_aw=(const float*)d_in[3], *t_ab=(const float*)d_in[4],
        *t_lg=(const float*)d_in[5], *t_lb=(const float*)d_in[6],
        *t_w1=(const float*)d_in[7], *t_b1=(const float*)d_in[8],
        *t_w2=(const float*)d_in[9], *t_b2=(const float*)d_in[10],
        *s_aw=(const float*)d_in[11], *s_ab=(const float*)d_in[12],
        *s_lg=(const float*)d_in[13], *s_lb=(const float*)d_in[14],
        *s_w1=(const float*)d_in[15], *s_b1=(const float*)d_in[16],
        *s_w2=(const float*)d_in[17], *s_b2=(const float*)d_in[18],
        *dw1=(const float*)d_in[19], *db1=(const float*)d_in[20],
        *bng=(const float*)d_in[21], *bnb=(const float*)d_in[22],
        *dw2=(const float*)d_in[23], *db2=(const float*)d_in[24];
    float* out = (float*)d_out;

    cudaFuncSetAttribute(bgemm_k<false,1,false>, cudaFuncAttributeMaxDynamicSharedMemorySize, SMEM_BG);
    cudaFuncSetAttribute(bgemm_k<true, 0,false>, cudaFuncAttributeMaxDynamicSharedMemorySize, SMEM_BG);
    cudaFuncSetAttribute(bgemm_k<false,2,false>, cudaFuncAttributeMaxDynamicSharedMemorySize, SMEM_BG);
    cudaFuncSetAttribute(bgemm_k<false,0,false>, cudaFuncAttributeMaxDynamicSharedMemorySize, SMEM_BG);
    cudaFuncSetAttribute(bgemm_k<false,0,true>,  cudaFuncAttributeMaxDynamicSharedMemorySize, SMEM_BG);

    float* S = nullptr;
    cudaGetSymbolAddress((void**)&S, g_scratch);
    float *sfeat=S+OFF_SFEAT, *qh=S+OFF_QH, *kh=S+OFF_KH, *vh=S+OFF_VH, *ob=S+OFF_O,
          *pb=S+OFF_P, *xb=S+OFF_X, *fb=S+OFF_F, *f2b=S+OFF_F2, *c1=S+OFF_C1,
          *c2=S+OFF_C2, *att=S+OFF_ATT, *hd=S+OFF_HD, *hbn=S+OFF_HBN;
    const size_t DD = (size_t)DMOD * DMOD;
    const long NDh = (long)NTOK * DH;

    selector_k<<<NTOK, 256>>>(feat, fid, mn, sfeat);

    auto run_enc = [&](const float* x0, const float* kvfix, bool selfa,
                       const float* aw, const float* ab, const float* lg, const float* lb,
                       const float* w1, const float* b1, const float* w2, const float* b2,
                       float* res) {
        const float* cur = x0;
        for (int l = 0; l < NLAY; l++) {
            const float* kv = selfa ? cur : kvfix;
            const float* W = aw + (size_t)l * 4 * DD;
            const float* Bb = ab + (size_t)l * 4 * DMOD;
            // fused QKV: z=0 uses cur, z=1,2 use kv; out -> qh|kh|vh (contiguous, sC=ND_)
            bgemm_k<false,1,false><<<dim3(32, 16, 3), 128, SMEM_BG>>>(cur, kv, W, Bb, qh,
                DMOD, DMOD, DMOD, 0, 0, (long)DD, (long)ND_, DMOD, 1.f);
            bgemm_k<true,0,false><<<dim3(16, 16, NHEAD), 128, SMEM_BG>>>(qh, qh, kh, nullptr, att,
                DH, DH, DH, NTOK, NDh, NDh, (long)NTOK * NTOK, 0, 0.0625f);
            softmax_k<<<NHEAD * NTOK, 256>>>(att);
            bgemm_k<false,2,false><<<dim3(4, 16, NHEAD), 128, SMEM_BG>>>(att, att, vh, nullptr, ob,
                NTOK, NTOK, DH, 0, (long)NTOK * NTOK, NDh, 0, 0, 1.f);
            bgemm_k<false,0,false><<<dim3(32, 16, 1), 128, SMEM_BG>>>(ob, ob, W + 3 * DD,
                Bb + 3 * DMOD, pb, DMOD, DMOD, DMOD, DMOD, 0, 0, 0, 0, 1.f);
            addln_k<<<NTOK, 256>>>(cur, pb, lg + (size_t)l * 2 * DMOD, lb + (size_t)l * 2 * DMOD, xb);
            bgemm_k<false,0,true><<<dim3(32, 16, 1), 128, SMEM_BG>>>(xb, xb,
                w1 + (size_t)l * DMOD * DFFN, b1 + (size_t)l * DFFN, fb,
                DMOD, DMOD, DFFN, DFFN, 0, 0, 0, 0, 1.f);
            bgemm_k<false,0,false><<<dim3(32, 16, 1), 128, SMEM_BG>>>(fb, fb,
                w2 + (size_t)l * DFFN * DMOD, b2 + (size_t)l * DMOD, f2b,
                DFFN, DFFN, DMOD, DMOD, 0, 0, 0, 0, 1.f);
            addln_k<<<NTOK, 256>>>(xb, f2b, lg + ((size_t)l * 2 + 1) * DMOD,
                                   lb + ((size_t)l * 2 + 1) * DMOD, res);
            cur = res;
        }
    };

    run_enc(feat, sfeat, false, t_aw, t_ab, t_lg, t_lb, t_w1, t_b1, t_w2, t_b2, c1);
    run_enc(c1, nullptr, true, s_aw, s_ab, s_lg, s_lb, s_w1, s_b1, s_w2, s_b2, c2);

    bgemm_k<false,0,false><<<dim3(16, 16, 1), 128, SMEM_BG>>>(c2, c2, dw1, db1, hd,
        DMOD, DMOD, DECH, DECH, 0, 0, 0, 0, 1.f);
    bn_k<<<DECH, 256>>>(hd, bng, bnb, hbn);
    dec2_k<<<(NTOK * NCLS1 + 255) / 256, 256>>>(hbn, dw2, db2, out + (size_t)NTOK * DMOD);
    cudaMemcpyAsync(out, c2, (size_t)NTOK * DMOD * sizeof(float), cudaMemcpyDeviceToDevice);
}

// round 14
// speedup vs baseline: 1.4114x; 1.4114x over previous
#include <cuda_runtime.h>
#include <math.h>
#include <stdint.h>

#define NTOK 1024
#define DMOD 2048
#define NHEAD 8
#define DH 256
#define NLAY 3
#define MM 16
#define KSEL 8
#define DFFN 2048
#define DECH 1024
#define NCLS1 35

static constexpr size_t ND_ = (size_t)NTOK * DMOD;
static constexpr size_t OFF_SFEAT = 0, OFF_QH = ND_, OFF_KH = 2*ND_, OFF_VH = 3*ND_,
    OFF_O = 4*ND_, OFF_P = 5*ND_, OFF_X = 6*ND_, OFF_F = 7*ND_, OFF_F2 = 8*ND_,
    OFF_C1 = 9*ND_, OFF_C2 = 10*ND_, OFF_ATT = 11*ND_;
static constexpr size_t OFF_HD  = OFF_ATT + (size_t)NHEAD*NTOK*NTOK;
static constexpr size_t OFF_HBN = OFF_HD + (size_t)NTOK*DECH;
static constexpr size_t SCR_FLOATS = OFF_HBN + (size_t)NTOK*DECH;
__device__ float g_scratch[SCR_FLOATS];

__device__ __forceinline__ float warpSum(float v) {
#pragma unroll
    for (int o = 16; o; o >>= 1) v += __shfl_down_sync(0xffffffffu, v, o);
    return v;
}
__device__ __forceinline__ float warpMax(float v) {
#pragma unroll
    for (int o = 16; o; o >>= 1) v = fmaxf(v, __shfl_down_sync(0xffffffffu, v, o));
    return v;
}
__device__ float blockSum(float v) {
    __shared__ float s[8];
    int lane = threadIdx.x & 31, w = threadIdx.x >> 5;
    v = warpSum(v);
    if (lane == 0) s[w] = v;
    __syncthreads();
    float r = 0.f;
    if (w == 0) { r = (lane < 8) ? s[lane] : 0.f; r = warpSum(r); }
    __syncthreads();
    return r;
}
__device__ float blockMax(float v) {
    __shared__ float s[8];
    int lane = threadIdx.x & 31, w = threadIdx.x >> 5;
    v = warpMax(v);
    if (lane == 0) s[w] = v;
    __syncthreads();
    float r = -1e30f;
    if (w == 0) { r = (lane < 8) ? s[lane] : -1e30f; r = warpMax(r); }
    __syncthreads();
    return r;
}

#define PECOEF (-0.008994473019508232f)

__global__ void selector_k(const float* __restrict__ feat, const int* __restrict__ fid,
                           const int* __restrict__ mn, float* __restrict__ sf) {
    int n = blockIdx.x, tid = threadIdx.x;
    __shared__ int nodes[MM], pos[MM], sel[KSEL];
    __shared__ float sc[MM], wgt[KSEL];
    if (tid < MM) nodes[tid] = mn[n * MM + tid];
    __syncthreads();
    if (tid == 0) {
        int p = 0, prev = fid[nodes[0]];
        pos[0] = 0;
        for (int m = 1; m < MM; m++) {
            int f = fid[nodes[m]];
            if (f != prev) { p++; prev = f; }
            pos[m] = p;
        }
    }
    __syncthreads();
    const float* fn = feat + (size_t)n * DMOD;
    float part[MM];
#pragma unroll
    for (int m = 0; m < MM; m++) part[m] = 0.f;
    for (int d = tid; d < DMOD; d += 256) {
        float fv = fn[d];
        float fr = expf((float)(d >> 1) * PECOEF);
        bool odd = d & 1;
#pragma unroll
        for (int m = 0; m < MM; m++) {
            float ang = (float)pos[m] * fr;
            float pev = odd ? cosf(ang) : sinf(ang);
            part[m] += fv * (feat[(size_t)nodes[m] * DMOD + d] + pev);
        }
    }
    for (int m = 0; m < MM; m++) {
        float ts = blockSum(part[m]);
        if (tid == 0) sc[m] = ts * 0.022097086912079608f;
    }
    __syncthreads();
    if (tid == 0) {
        unsigned used = 0;
        float tv[KSEL];
        for (int k = 0; k < KSEL; k++) {
            float best = -1e30f; int bi = 0;
            for (int m = 0; m < MM; m++)
                if (!((used >> m) & 1) && sc[m] > best) { best = sc[m]; bi = m; }
            used |= 1u << bi; sel[k] = bi; tv[k] = best;
        }
        float mx = tv[0], ssum = 0.f;
        for (int k = 0; k < KSEL; k++) { wgt[k] = expf(tv[k] - mx); ssum += wgt[k]; }
        for (int k = 0; k < KSEL; k++) wgt[k] /= ssum;
    }
    __syncthreads();
    float* po = sf + (size_t)n * DMOD;
    for (int d = tid; d < DMOD; d += 256) {
        float fr = expf((float)(d >> 1) * PECOEF);
        bool odd = d & 1;
        float acc = 0.f;
#pragma unroll
        for (int k = 0; k < KSEL; k++) {
            int m = sel[k];
            float ang = (float)pos[m] * fr;
            float pev = odd ? cosf(ang) : sinf(ang);
            acc += wgt[k] * (feat[(size_t)nodes[m] * DMOD + d] + pev);
        }
        po[d] = acc;
    }
}

// ===== bf16-3-product GEMM, 128x128 tile, ks-pipelined fragments =====
__device__ __forceinline__ uint32_t smem_u32(const void* p) {
    uint32_t a;
    asm("{ .reg .u64 t; cvta.to.shared.u64 t, %1; cvt.u32.u64 %0, t; }" : "=r"(a) : "l"(p));
    return a;
}
__device__ __forceinline__ float bf_lo(uint32_t w) { return __uint_as_float(w << 16); }
__device__ __forceinline__ float bf_hi(uint32_t w) { return __uint_as_float(w & 0xffff0000u); }
__device__ __forceinline__ uint32_t packbf(float x, float y) {
    uint32_t r;
    asm("cvt.rn.satfinite.bf16x2.f32 %0, %1, %2;" : "=r"(r) : "f"(y), "f"(x));
    return r;
}
__device__ __forceinline__ void split2(float x, float y, uint32_t& hi, uint32_t& lo) {
    hi = packbf(x, y);
    lo = packbf(x - bf_lo(hi), y - bf_hi(hi));
}
__device__ __forceinline__ void sts128(uint32_t a, uint32_t x, uint32_t y, uint32_t z, uint32_t w) {
    asm volatile("st.shared.v4.b32 [%0], {%1,%2,%3,%4};" :: "r"(a), "r"(x), "r"(y), "r"(z), "r"(w) : "memory");
}
__device__ __forceinline__ void sts32(uint32_t a, uint32_t x) {
    asm volatile("st.shared.b32 [%0], %1;" :: "r"(a), "r"(x) : "memory");
}
#define LDMX4(r0, r1, r2, r3, ad)                                             \
    asm volatile("ldmatrix.sync.aligned.m8n8.x4.shared.b16 {%0,%1,%2,%3}, [%4];" \
                 : "=r"(r0), "=r"(r1), "=r"(r2), "=r"(r3) : "r"(ad))
#define MMA_BF16(c, a, b)                                                     \
    asm volatile(                                                             \
        "mma.sync.aligned.m16n8k16.row.col.f32.bf16.bf16.f32 "                \
        "{%0,%1,%2,%3},{%4,%5,%6,%7},{%8,%9},{%0,%1,%2,%3};\n"                \
        : "+f"(c[0]), "+f"(c[1]), "+f"(c[2]), "+f"(c[3])                      \
        : "r"(a[0]), "r"(a[1]), "r"(a[2]), "r"(a[3]), "r"(b[0]), "r"(b[1]))

// stage 40960B: A_hi@0 A_lo@10240 B_hi@20480 B_lo@30720; rows stride 80B (40 bf16)
#define SMEM_BG 81920

// OM=0: C[bz*sC + m*ldc + n] | OM=1: bz*sC + split-head | OM=2: merge-head
template <bool TB, int OM, bool RELU>
__global__ void __launch_bounds__(256)
bgemm_k(const float* __restrict__ A0, const float* __restrict__ A1,
        const float* __restrict__ B,
        const float* __restrict__ bias, float* __restrict__ C,
        int K, int lda, int ldb, int ldc,
        long sA, long sB, long sC, long sBias, float scale) {
    extern __shared__ __align__(16) char sm8[];
    int bz = blockIdx.z;
    const float* Ab = ((bz == 0) ? A0 : A1) + (long)bz * sA;
    const float* Bb = B + (long)bz * sB;
    int m0 = blockIdx.y * 128, n0 = blockIdx.x * 128;
    int tid = threadIdx.x;
    int warpId = tid >> 5, lane = tid & 31;
    int g = lane >> 2, tig = lane & 3;
    int wm = warpId & 1, wn = warpId >> 1;
    int mBase = wm * 64, nBase = wn * 32;
    uint32_t smb = smem_u32(sm8);

    int arow = tid >> 1, akh = (tid & 1) * 16;
    int bkp = tid & 15, bnj = tid >> 4;

    float4 la[4], lb[4];
    auto ldgChunk = [&](int ch) {
        int k0 = ch << 5;
        const float4* ap = (const float4*)(Ab + (long)(m0 + arow) * lda + k0 + akh);
        la[0] = ap[0]; la[1] = ap[1]; la[2] = ap[2]; la[3] = ap[3];
        if (TB) {
            const float4* bp = (const float4*)(Bb + (long)(n0 + arow) * ldb + k0 + akh);
            lb[0] = bp[0]; lb[1] = bp[1]; lb[2] = bp[2]; lb[3] = bp[3];
        } else {
            const float4* bp = (const float4*)(Bb + (long)(k0 + 2 * bkp) * ldb + n0 + bnj * 8);
            lb[0] = bp[0]; lb[1] = bp[1];
            const float4* bp2 = (const float4*)(Bb + (long)(k0 + 2 * bkp + 1) * ldb + n0 + bnj * 8);
            lb[2] = bp2[0]; lb[3] = bp2[1];
        }
    };
    auto stsChunk = [&](int st) {
        uint32_t sb = smb + (uint32_t)st * 40960u;
        uint32_t hi[8], lo[8];
        const float* fa = (const float*)la;
#pragma unroll
        for (int i = 0; i < 8; i++) split2(fa[2 * i], fa[2 * i + 1], hi[i], lo[i]);
        uint32_t aoff = sb + (uint32_t)(arow * 80 + akh * 2);
        sts128(aoff,           hi[0], hi[1], hi[2], hi[3]);
        sts128(aoff + 16u,     hi[4], hi[5], hi[6], hi[7]);
        sts128(aoff + 10240u,       lo[0], lo[1], lo[2], lo[3]);
        sts128(aoff + 10240u + 16u, lo[4], lo[5], lo[6], lo[7]);
        const float* fb = (const float*)lb;
        if (TB) {
#pragma unroll
            for (int i = 0; i < 8; i++) split2(fb[2 * i], fb[2 * i + 1], hi[i], lo[i]);
            uint32_t boff = sb + 20480u + (uint32_t)(arow * 80 + akh * 2);
            sts128(boff,           hi[0], hi[1], hi[2], hi[3]);
            sts128(boff + 16u,     hi[4], hi[5], hi[6], hi[7]);
            sts128(boff + 10240u,       lo[0], lo[1], lo[2], lo[3]);
            sts128(boff + 10240u + 16u, lo[4], lo[5], lo[6], lo[7]);
        } else {
#pragma unroll
            for (int n = 0; n < 8; n++) {
                uint32_t h, l;
                split2(fb[n], fb[8 + n], h, l);
                uint32_t boff = sb + 20480u + (uint32_t)((bnj * 8 + n) * 80 + bkp * 4);
                sts32(boff, h);
                sts32(boff + 10240u, l);
            }
        }
    };

    float acc[4][4][4];
#pragma unroll
    for (int i = 0; i < 4; i++)
#pragma unroll
        for (int j = 0; j < 4; j++)
#pragma unroll
            for (int r = 0; r < 4; r++) acc[i][j][r] = 0.f;

    int lrow = lane & 7, lgrp = lane >> 3;

    // fragment sets for ks pipelining
    uint32_t ahi[2][4][4], alo[2][4][4], bhi[2][4][2], blo[2][4][2];
    auto loadFrags = [&](uint32_t sb, int ks, int buf) {
        int kbA = ks * 32 + (lgrp >> 1) * 16;
        int rA = (lgrp & 1) * 8 + lrow;
#pragma unroll
        for (int mi = 0; mi < 4; mi++) {
            uint32_t ad = sb + (uint32_t)((mBase + mi * 16 + rA) * 80 + kbA);
            LDMX4(ahi[buf][mi][0], ahi[buf][mi][1], ahi[buf][mi][2], ahi[buf][mi][3], ad);
            LDMX4(alo[buf][mi][0], alo[buf][mi][1], alo[buf][mi][2], alo[buf][mi][3], ad + 10240u);
        }
        int kbB = ks * 32 + (lgrp & 1) * 16;
        int rB = (lgrp >> 1) * 8 + lrow;
#pragma unroll
        for (int np = 0; np < 2; np++) {
            uint32_t bd = sb + 20480u + (uint32_t)((nBase + np * 16 + rB) * 80 + kbB);
            LDMX4(bhi[buf][2*np][0], bhi[buf][2*np][1], bhi[buf][2*np+1][0], bhi[buf][2*np+1][1], bd);
            LDMX4(blo[buf][2*np][0], blo[buf][2*np][1], blo[buf][2*np+1][0], blo[buf][2*np+1][1], bd + 10240u);
        }
    };
    auto mmaBlock = [&](int buf) {
#pragma unroll
        for (int mi = 0; mi < 4; mi++)
#pragma unroll
            for (int ni = 0; ni < 4; ni++) {
                MMA_BF16(acc[mi][ni], ahi[buf][mi], bhi[buf][ni]);
                MMA_BF16(acc[mi][ni], ahi[buf][mi], blo[buf][ni]);
                MMA_BF16(acc[mi][ni], alo[buf][mi], bhi[buf][ni]);
            }
    };

    int nc = K >> 5;
    ldgChunk(0);
    stsChunk(0);
    __syncthreads();
    for (int ch = 0; ch < nc; ch++) {
        uint32_t sb = smb + (uint32_t)(ch & 1) * 40960u;
        if (ch + 1 < nc) ldgChunk(ch + 1);
        loadFrags(sb, 0, 0);
        loadFrags(sb, 1, 1);   // issued before MMAs; covered by first MMA block
        mmaBlock(0);
        mmaBlock(1);
        if (ch + 1 < nc) stsChunk((ch + 1) & 1);   // other stage; prior readers fenced last iter
        __syncthreads();
    }

    const float* bp = bias ? (bias + (long)bz * sBias) : nullptr;
#pragma unroll
    for (int mi = 0; mi < 4; mi++) {
#pragma unroll
        for (int ni = 0; ni < 4; ni++) {
            int row0 = m0 + mBase + mi * 16 + g;
            int col0 = n0 + nBase + ni * 8 + tig * 2;
#pragma unroll
            for (int h = 0; h < 2; h++) {
                int row = row0 + 8 * h;
                float vx = acc[mi][ni][2 * h + 0] * scale;
                float vy = acc[mi][ni][2 * h + 1] * scale;
                if (bp) { vx += bp[col0]; vy += bp[col0 + 1]; }
                if (RELU) { vx = fmaxf(vx, 0.f); vy = fmaxf(vy, 0.f); }
                long idx;
                if (OM == 0)      idx = (long)bz * sC + (long)row * ldc + col0;
                else if (OM == 1) idx = (long)bz * sC + ((long)(col0 >> 8) * NTOK + row) * DH + (col0 & 255);
                else              idx = (long)row * DMOD + (long)bz * DH + col0;
                C[idx] = vx;
                C[idx + 1] = vy;
            }
        }
    }
}

__global__ void softmax_k(float* __restrict__ att) {
    float* row = att + (long)blockIdx.x * 1024;
    int tid = threadIdx.x;
    float v[4], mx = -1e30f;
#pragma unroll
    for (int i = 0; i < 4; i++) { v[i] = row[tid + i * 256]; mx = fmaxf(mx, v[i]); }
    float bm = blockMax(mx);
    __shared__ float sb, sv;
    if (tid == 0) sb = bm;
    __syncthreads();
    mx = sb;
    float s = 0.f;
#pragma unroll
    for (int i = 0; i < 4; i++) { v[i] = expf(v[i] - mx); s += v[i]; }
    float bs = blockSum(s);
    if (tid == 0) sv = 1.f / bs;
    __syncthreads();
#pragma unroll
    for (int i = 0; i < 4; i++) row[tid + i * 256] = v[i] * sv;
}

__global__ void addln_k(const float* __restrict__ a, const float* __restrict__ b,
                        const float* __restrict__ g, const float* __restrict__ be,
                        float* __restrict__ o) {
    int n = blockIdx.x, tid = threadIdx.x;
    const float* pa = a + (size_t)n * DMOD;
    const float* pb = b + (size_t)n * DMOD;
    float x[8], s = 0.f;
#pragma unroll
    for (int i = 0; i < 8; i++) { int d = tid + i * 256; x[i] = pa[d] + pb[d]; s += x[i]; }
    float ts = blockSum(s);
    __shared__ float mu, inv;
    if (tid == 0) mu = ts * (1.f / DMOD);
    __syncthreads();
    float m = mu, vs = 0.f;
#pragma unroll
    for (int i = 0; i < 8; i++) { float dv = x[i] - m; vs += dv * dv; }
    float tv = blockSum(vs);
    if (tid == 0) inv = rsqrtf(tv * (1.f / DMOD) + 1e-5f);
    __syncthreads();
    float iv = inv;
    float* po = o + (size_t)n * DMOD;
#pragma unroll
    for (int i = 0; i < 8; i++) { int d = tid + i * 256; po[d] = (x[i] - m) * iv * g[d] + be[d]; }
}

__global__ void bn_k(const float* __restrict__ h, const float* __restrict__ g,
                     const float* __restrict__ b, float* __restrict__ o) {
    int j = blockIdx.x, tid = threadIdx.x;
    float s = 0.f;
    for (int r = tid; r < NTOK; r += 256) s += h[(size_t)r * DECH + j];
    float ts = blockSum(s);
    __shared__ float mu, inv;
    if (tid == 0) mu = ts * (1.f / NTOK);
    __syncthreads();
    float m = mu, vs = 0.f;
    for (int r = tid; r < NTOK; r += 256) { float d = h[(size_t)r * DECH + j] - m; vs += d * d; }
    float tv = blockSum(vs);
    if (tid == 0) inv = rsqrtf(tv * (1.f / NTOK) + 1e-5f);
    __syncthreads();
    float iv = inv, gg = g[j], bb = b[j];
    for (int r = tid; r < NTOK; r += 256) {
        float v = (h[(size_t)r * DECH + j] - m) * iv * gg + bb;
        o[(size_t)r * DECH + j] = fmaxf(v, 0.f);
    }
}

__global__ void dec2_k(const float* __restrict__ hbn, const float* __restrict__ w,
                       const float* __restrict__ b, float* __restrict__ dist) {
    int idx = blockIdx.x * blockDim.x + threadIdx.x;
    if (idx >= NTOK * NCLS1) return;
    int n = idx / NCLS1, c = idx % NCLS1;
    const float* hr = hbn + (size_t)n * DECH;
    float s = 0.f;
    for (int j = 0; j < DECH; j++) s = fmaf(hr[j], w[(size_t)j * NCLS1 + c], s);
    dist[idx] = s + b[c];
}

extern "C" void kernel_launch(void* const* d_in, const int* in_sizes, int n_in,
                              void* d_out, int out_size) {
    const float* feat = (const float*)d_in[0];
    const int* fid = (const int*)d_in[1];
    const int* mn = (const int*)d_in[2];
    const float *t_aw=(const float*)d_in[3], *t_ab=(const float*)d_in[4],
        *t_lg=(const float*)d_in[5], *t_lb=(const float*)d_in[6],
        *t_w1=(const float*)d_in[7], *t_b1=(const float*)d_in[8],
        *t_w2=(const float*)d_in[9], *t_b2=(const float*)d_in[10],
        *s_aw=(const float*)d_in[11], *s_ab=(const float*)d_in[12],
        *s_lg=(const float*)d_in[13], *s_lb=(const float*)d_in[14],
        *s_w1=(const float*)d_in[15], *s_b1=(const float*)d_in[16],
        *s_w2=(const float*)d_in[17], *s_b2=(const float*)d_in[18],
        *dw1=(const float*)d_in[19], *db1=(const float*)d_in[20],
        *bng=(const float*)d_in[21], *bnb=(const float*)d_in[22],
        *dw2=(const float*)d_in[23], *db2=(const float*)d_in[24];
    float* out = (float*)d_out;

    cudaFuncSetAttribute(bgemm_k<false,1,false>, cudaFuncAttributeMaxDynamicSharedMemorySize, SMEM_BG);
    cudaFuncSetAttribute(bgemm_k<true, 0,false>, cudaFuncAttributeMaxDynamicSharedMemorySize, SMEM_BG);
    cudaFuncSetAttribute(bgemm_k<false,2,false>, cudaFuncAttributeMaxDynamicSharedMemorySize, SMEM_BG);
    cudaFuncSetAttribute(bgemm_k<false,0,false>, cudaFuncAttributeMaxDynamicSharedMemorySize, SMEM_BG);
    cudaFuncSetAttribute(bgemm_k<false,0,true>,  cudaFuncAttributeMaxDynamicSharedMemorySize, SMEM_BG);

    float* S = nullptr;
    cudaGetSymbolAddress((void**)&S, g_scratch);
    float *sfeat=S+OFF_SFEAT, *qh=S+OFF_QH, *kh=S+OFF_KH, *vh=S+OFF_VH, *ob=S+OFF_O,
          *pb=S+OFF_P, *xb=S+OFF_X, *fb=S+OFF_F, *f2b=S+OFF_F2, *c1=S+OFF_C1,
          *c2=S+OFF_C2, *att=S+OFF_ATT, *hd=S+OFF_HD, *hbn=S+OFF_HBN;
    const size_t DD = (size_t)DMOD * DMOD;
    const long NDh = (long)NTOK * DH;

    selector_k<<<NTOK, 256>>>(feat, fid, mn, sfeat);

    auto run_enc = [&](const float* x0, const float* kvfix, bool selfa,
                       const float* aw, const float* ab, const float* lg, const float* lb,
                       const float* w1, const float* b1, const float* w2, const float* b2,
                       float* res) {
        const float* cur = x0;
        for (int l = 0; l < NLAY; l++) {
            const float* kv = selfa ? cur : kvfix;
            const float* W = aw + (size_t)l * 4 * DD;
            const float* Bb = ab + (size_t)l * 4 * DMOD;
            bgemm_k<false,1,false><<<dim3(16, 8, 3), 256, SMEM_BG>>>(cur, kv, W, Bb, qh,
                DMOD, DMOD, DMOD, 0, 0, (long)DD, (long)ND_, DMOD, 1.f);
            bgemm_k<true,0,false><<<dim3(8, 8, NHEAD), 256, SMEM_BG>>>(qh, qh, kh, nullptr, att,
                DH, DH, DH, NTOK, NDh, NDh, (long)NTOK * NTOK, 0, 0.0625f);
            softmax_k<<<NHEAD * NTOK, 256>>>(att);
            bgemm_k<false,2,false><<<dim3(2, 8, NHEAD), 256, SMEM_BG>>>(att, att, vh, nullptr, ob,
                NTOK, NTOK, DH, 0, (long)NTOK * NTOK, NDh, 0, 0, 1.f);
            bgemm_k<false,0,false><<<dim3(16, 8, 1), 256, SMEM_BG>>>(ob, ob, W + 3 * DD,
                Bb + 3 * DMOD, pb, DMOD, DMOD, DMOD, DMOD, 0, 0, 0, 0, 1.f);
            addln_k<<<NTOK, 256>>>(cur, pb, lg + (size_t)l * 2 * DMOD, lb + (size_t)l * 2 * DMOD, xb);
            bgemm_k<false,0,true><<<dim3(16, 8, 1), 256, SMEM_BG>>>(xb, xb,
                w1 + (size_t)l * DMOD * DFFN, b1 + (size_t)l * DFFN, fb,
                DMOD, DMOD, DFFN, DFFN, 0, 0, 0, 0, 1.f);
            bgemm_k<false,0,false><<<dim3(16, 8, 1), 256, SMEM_BG>>>(fb, fb,
                w2 + (size_t)l * DFFN * DMOD, b2 + (size_t)l * DMOD, f2b,
                DFFN, DFFN, DMOD, DMOD, 0, 0, 0, 0, 1.f);
            addln_k<<<NTOK, 256>>>(xb, f2b, lg + ((size_t)l * 2 + 1) * DMOD,
                                   lb + ((size_t)l * 2 + 1) * DMOD, res);
            cur = res;
        }
    };

    run_enc(feat, sfeat, false, t_aw, t_ab, t_lg, t_lb, t_w1, t_b1, t_w2, t_b2, c1);
    run_enc(c1, nullptr, true, s_aw, s_ab, s_lg, s_lb, s_w1, s_b1, s_w2, s_b2, c2);

    bgemm_k<false,0,false><<<dim3(8, 8, 1), 256, SMEM_BG>>>(c2, c2, dw1, db1, hd,
        DMOD, DMOD, DECH, DECH, 0, 0, 0, 0, 1.f);
    bn_k<<<DECH, 256>>>(hd, bng, bnb, hbn);
    dec2_k<<<(NTOK * NCLS1 + 255) / 256, 256>>>(hbn, dw2, db2, out + (size_t)NTOK * DMOD);
    cudaMemcpyAsync(out, c2, (size_t)NTOK * DMOD * sizeof(float), cudaMemcpyDeviceToDevice);
}